// round 16
// baseline (speedup 1.0000x reference)
#include <cuda_runtime.h>
#include <math.h>

// PSRoIPool (R-FCN), d-vectorized, ONE WARP per bin, one bin-row per block.
// R15 = R13 (tied-best 6.62us) + adaptive lane tile: warps pick 8w x 4h for
// wide bins or 4w x 8h for narrow bins (bwc <= 4). bwc is warp-uniform, so
// the choice is divergence-free; it halves mainloop rounds for tall-narrow
// bins. Structure unchanged: single kernel node, single wave
// (896 blocks x 7 warps = 6272 warps, ~42/SM all co-resident).
//
//   rois:     [N=128, 5]  (batch_idx, x1, y1, x2, y2)  float32
//   features: [B=2, C=392, H=50, W=84]                  float32
//   out:      [N, D=8, G=7, G=7]                        float32

#define G   7
#define D   8
#define Hf  50
#define Wf  84
#define HW  (Hf * Wf)           // 4200
#define Cf  (D * G * G)         // 392
#define DSTRIDE (G * G * HW)    // 205800 floats between d-channels (fits LDG imm)

__global__ __launch_bounds__(G * 32) void psroi_warp_at_kernel(
    const float* __restrict__ rois,
    const float* __restrict__ feat,
    float* __restrict__ out,
    float scale)
{
    const int i = blockIdx.x;         // bin row 0..6
    const int n = blockIdx.y;         // roi
    const int t = threadIdx.x;        // 0..223

    const int lane = t & 31;
    const int j    = t >> 5;          // bin col 0..6 (one warp per bin)
    const int ij   = i * G + j;       // channel block offset

    // ---- per-thread geometry (warp-uniform rois load, L1-resident) ----
    const float* r = rois + n * 5;
    const int   b  = (int)__ldg(r + 0);
    const float xs = rintf(__ldg(r + 1)) * scale;
    const float ys = rintf(__ldg(r + 2)) * scale;
    const float xe = (rintf(__ldg(r + 3)) + 1.0f) * scale;
    const float ye = (rintf(__ldg(r + 4)) + 1.0f) * scale;

    const float bw = fmaxf(xe - xs, 0.1f) * (1.0f / (float)G);
    const float bh = fmaxf(ye - ys, 0.1f) * (1.0f / (float)G);

    const int ws = (int)fminf(fmaxf(floorf((float)j * bw + xs), 0.0f), (float)Wf);
    const int we = (int)fminf(fmaxf(ceilf(((float)j + 1.0f) * bw + xs), 0.0f), (float)Wf);
    const int hs = (int)fminf(fmaxf(floorf((float)i * bh + ys), 0.0f), (float)Hf);
    const int he = (int)fminf(fmaxf(ceilf(((float)i + 1.0f) * bh + ys), 0.0f), (float)Hf);

    const int bwc = we - ws;          // warp-uniform bin width
    const float area = fmaxf((float)((he - hs) * bwc), 1.0f);

    // Adaptive lane tile (divergence-free: bwc uniform across the warp):
    //   wide bins  (bwc > 4): 8 lanes across w, 4 across h
    //   narrow bins(bwc <= 4): 4 lanes across w, 8 across h
    const int lw     = (bwc <= 4) ? 2 : 3;   // log2(lanes across w)
    const int wstep  = 1 << lw;              // 4 or 8
    const int hstep  = 32 >> lw;             // 8 or 4

    const int h0 = hs + (lane >> lw);
    const int w0 = ws + (lane & (wstep - 1));
    const int nh = (he - h0 + hstep - 1) >> (5 - lw);  // ceil-div by hstep
    const int nw = (we - w0 + wstep - 1) >> lw;        // ceil-div by wstep

    float acc[D];
    #pragma unroll
    for (int d = 0; d < D; ++d) acc[d] = 0.0f;

    if (nh > 0 && nw > 0) {
        const float* rowp = feat + (b * Cf + ij) * HW + h0 * Wf + w0;
        const int rstride = hstep * Wf;
        for (int hc = nh; hc > 0; --hc, rowp += rstride) {
            const float* px = rowp;
            for (int wc = nw; wc > 0; --wc, px += wstep) {
                #pragma unroll
                for (int d = 0; d < D; ++d)
                    acc[d] += __ldg(px + d * DSTRIDE);   // LDG [R+imm]
            }
        }
    }

    // ---- reduce-scatter butterfly over the full warp ----
    const unsigned gmask = 0xFFFFFFFFu;
    const int b0 = lane & 1, b1 = (lane >> 1) & 1, b2 = (lane >> 2) & 1;

    // level 1 (xor 1): keep d with bit0(d)==b0           -> 4 values
    float v1[4];
    #pragma unroll
    for (int k = 0; k < 4; ++k) {
        float keep = b0 ? acc[2 * k + 1] : acc[2 * k];
        float send = b0 ? acc[2 * k]     : acc[2 * k + 1];
        v1[k] = keep + __shfl_xor_sync(gmask, send, 1);
    }
    // level 2 (xor 2): keep k with bit0(k)==b1           -> 2 values
    float v2[2];
    #pragma unroll
    for (int m = 0; m < 2; ++m) {
        float keep = b1 ? v1[2 * m + 1] : v1[2 * m];
        float send = b1 ? v1[2 * m]     : v1[2 * m + 1];
        v2[m] = keep + __shfl_xor_sync(gmask, send, 2);
    }
    // level 3 (xor 4): keep m==b2                         -> 1 value, d = lane&7
    float v;
    {
        float keep = b2 ? v2[1] : v2[0];
        float send = b2 ? v2[0] : v2[1];
        v = keep + __shfl_xor_sync(gmask, send, 4);
    }
    // levels 4,5 (xor 8, xor 16): fold the four 8-lane replicas
    v += __shfl_xor_sync(gmask, v, 8);
    v += __shfl_xor_sync(gmask, v, 16);

    // lanes 0..7 write output d = lane:  out[n*Cf + d*49 + ij]
    if (lane < D)
        out[n * Cf + lane * (G * G) + ij] = __fdividef(v, area);
}

extern "C" void kernel_launch(void* const* d_in, const int* in_sizes, int n_in,
                              void* d_out, int out_size)
{
    const float* rois = (const float*)d_in[0];
    const float* feat = (const float*)d_in[1];
    (void)n_in; (void)out_size;

    const int stride = 16;                 // scalar input, constant for this problem
    const int N = in_sizes[0] / 5;         // 128
    float scale = 1.0f / (float)stride;

    dim3 grid(G, N);                       // (7, 128) = 896 blocks, single node
    psroi_warp_at_kernel<<<grid, G * 32>>>(rois, feat, (float*)d_out, scale);
}

// round 17
// speedup vs baseline: 1.0292x; 1.0292x over previous
#include <cuda_runtime.h>
#include <math.h>

// PSRoIPool (R-FCN), d-vectorized, ONE WARP per bin, one bin-row per block.
// FINAL (R13 config, measured 6.624us best of 15 variants):
//  - grid (7, N=128) x 224 threads = 6272 warps -> ONE wave (~42 warps/SM,
//    all co-resident; any split beyond this causes a 2nd wave, +2.3us).
//  - single kernel node (any extra graph node costs ~2us on replay).
//  - warp-per-bin, lanes tile the bin 8-wide (w) x 4-high (h): the 8 w-lanes
//    read one contiguous 32B sector per channel; 8 channel loads per pixel
//    (channel = d*49 + i*7 + j, stride 49*H*W -> LDG [R+imm]) give MLP=8.
//  - strength-reduced loop: running pointers + count-based exits; fixed
//    strides keep ptxas in the uniform path (regs=31).
//  - per-thread geometry (no smem/barrier prologue), 8-shfl reduce-scatter
//    butterfly leaves d=lane on lanes 0..7.
//
//   rois:     [N=128, 5]  (batch_idx, x1, y1, x2, y2)  float32
//   features: [B=2, C=392, H=50, W=84]                  float32
//   out:      [N, D=8, G=7, G=7]                        float32

#define G   7
#define D   8
#define Hf  50
#define Wf  84
#define HW  (Hf * Wf)           // 4200
#define Cf  (D * G * G)         // 392
#define DSTRIDE (G * G * HW)    // 205800 floats between d-channels (fits LDG imm)

__global__ __launch_bounds__(G * 32) void psroi_warp_sr_kernel(
    const float* __restrict__ rois,
    const float* __restrict__ feat,
    float* __restrict__ out,
    float scale)
{
    const int i = blockIdx.x;         // bin row 0..6
    const int n = blockIdx.y;         // roi
    const int t = threadIdx.x;        // 0..223

    const int lane = t & 31;
    const int j    = t >> 5;          // bin col 0..6 (one warp per bin)
    const int ij   = i * G + j;       // channel block offset

    // ---- per-thread geometry (warp-uniform rois load, L1-resident) ----
    const float* r = rois + n * 5;
    const int   b  = (int)__ldg(r + 0);
    const float xs = rintf(__ldg(r + 1)) * scale;
    const float ys = rintf(__ldg(r + 2)) * scale;
    const float xe = (rintf(__ldg(r + 3)) + 1.0f) * scale;
    const float ye = (rintf(__ldg(r + 4)) + 1.0f) * scale;

    const float bw = fmaxf(xe - xs, 0.1f) * (1.0f / (float)G);
    const float bh = fmaxf(ye - ys, 0.1f) * (1.0f / (float)G);

    const int ws = (int)fminf(fmaxf(floorf((float)j * bw + xs), 0.0f), (float)Wf);
    const int we = (int)fminf(fmaxf(ceilf(((float)j + 1.0f) * bw + xs), 0.0f), (float)Wf);
    const int hs = (int)fminf(fmaxf(floorf((float)i * bh + ys), 0.0f), (float)Hf);
    const int he = (int)fminf(fmaxf(ceilf(((float)i + 1.0f) * bh + ys), 0.0f), (float)Hf);

    const float area = fmaxf((float)((he - hs) * (we - ws)), 1.0f);

    // This lane's tile position: 8 lanes across w, 4 across h.
    const int h0 = hs + (lane >> 3);
    const int w0 = ws + (lane & 7);
    // Iteration counts (ceil-div of remaining extent; <=0 means no work).
    const int nh = (he - h0 + 3) >> 2;      // rows this lane visits (stride 4)
    const int nw = (we - w0 + 7) >> 3;      // cols this lane visits (stride 8)

    float acc[D];
    #pragma unroll
    for (int d = 0; d < D; ++d) acc[d] = 0.0f;

    if (nh > 0 && nw > 0) {
        const float* rowp = feat + (b * Cf + ij) * HW + h0 * Wf + w0;
        for (int hc = nh; hc > 0; --hc, rowp += 4 * Wf) {
            const float* px = rowp;
            for (int wc = nw; wc > 0; --wc, px += 8) {
                #pragma unroll
                for (int d = 0; d < D; ++d)
                    acc[d] += __ldg(px + d * DSTRIDE);   // LDG [R+imm]
            }
        }
    }

    // ---- reduce-scatter butterfly over the full warp ----
    const unsigned gmask = 0xFFFFFFFFu;
    const int b0 = lane & 1, b1 = (lane >> 1) & 1, b2 = (lane >> 2) & 1;

    // level 1 (xor 1): keep d with bit0(d)==b0           -> 4 values
    float v1[4];
    #pragma unroll
    for (int k = 0; k < 4; ++k) {
        float keep = b0 ? acc[2 * k + 1] : acc[2 * k];
        float send = b0 ? acc[2 * k]     : acc[2 * k + 1];
        v1[k] = keep + __shfl_xor_sync(gmask, send, 1);
    }
    // level 2 (xor 2): keep k with bit0(k)==b1           -> 2 values
    float v2[2];
    #pragma unroll
    for (int m = 0; m < 2; ++m) {
        float keep = b1 ? v1[2 * m + 1] : v1[2 * m];
        float send = b1 ? v1[2 * m]     : v1[2 * m + 1];
        v2[m] = keep + __shfl_xor_sync(gmask, send, 2);
    }
    // level 3 (xor 4): keep m==b2                         -> 1 value, d = lane&7
    float v;
    {
        float keep = b2 ? v2[1] : v2[0];
        float send = b2 ? v2[0] : v2[1];
        v = keep + __shfl_xor_sync(gmask, send, 4);
    }
    // levels 4,5 (xor 8, xor 16): fold the four 8-lane replicas
    v += __shfl_xor_sync(gmask, v, 8);
    v += __shfl_xor_sync(gmask, v, 16);

    // lanes 0..7 write output d = lane:  out[n*Cf + d*49 + ij]
    if (lane < D)
        out[n * Cf + lane * (G * G) + ij] = __fdividef(v, area);
}

extern "C" void kernel_launch(void* const* d_in, const int* in_sizes, int n_in,
                              void* d_out, int out_size)
{
    const float* rois = (const float*)d_in[0];
    const float* feat = (const float*)d_in[1];
    (void)n_in; (void)out_size;

    const int stride = 16;                 // scalar input, constant for this problem
    const int N = in_sizes[0] / 5;         // 128
    float scale = 1.0f / (float)stride;

    dim3 grid(G, N);                       // (7, 128) = 896 blocks, single node
    psroi_warp_sr_kernel<<<grid, G * 32>>>(rois, feat, (float*)d_out, scale);
}